// round 6
// baseline (speedup 1.0000x reference)
#include <cuda_runtime.h>

#define BB 2
#define DD 192
#define HH 56
#define WW 56
#define LL 3136
#define NN 16
#define RR 12
#define KK 4
#define CDIM 44   /* R + 2N */

#define TL 49     /* proj tile length; 64 tiles * 49 = 3136 */
#define NTILE 64
#define XPITCH 52 /* smem pitch (even, mult of 4) */

#define TC 28     /* scan chunk length */
#define NCH 112   /* 112 * 28 = 3136 */
#define TG 4      /* load-pipeline group: 28 = 7*4 */

#define LOG2E 1.44269504088896341f

// ---------------- scratch (device globals; no runtime alloc) ----------------
__device__ float g_xT[2*BB*DD*LL];
__device__ float g_u[2*(size_t)BB*KK*LL*DD];
__device__ float g_delta[2*(size_t)BB*KK*LL*DD];
__device__ float g_Bm[2*BB*KK*LL*NN];
__device__ float g_Cm[2*BB*KK*LL*NN];
__device__ float g_ys[2*(size_t)BB*KK*LL*DD];
__device__ float g_carry[2*(size_t)BB*KK*DD*NCH*2*NN];
__device__ float g_hin[2*(size_t)BB*KK*DD*NCH*NN];
__device__ float g_A[2*KK*DD*NN];

// ---------------- kernel 0: precompute A ------------------------------------
__global__ void k_prepA(const float* __restrict__ A1logs, const float* __restrict__ A2logs) {
    int g = blockIdx.x*blockDim.x + threadIdx.x;
    if (g >= 2*KK*DD*NN) return;
    int s = g / (KK*DD*NN);
    int rem = g % (KK*DD*NN);
    const float* src = (s == 0) ? A1logs : A2logs;
    g_A[g] = -expf(src[rem]) * LOG2E;
}

// ---------------- kernel 1: spatial transpose -------------------------------
__global__ void k_transpose(const float* __restrict__ x1, const float* __restrict__ x2) {
    __shared__ float sm[HH*57];
    int bi = blockIdx.x;
    int d = bi % DD;
    int b = (bi / DD) % BB;
    int s = bi / (DD*BB);
    const float* src = ((s == 0) ? x1 : x2) + ((size_t)b*DD + d)*LL;
    float* dst = g_xT + ((size_t)(s*BB + b)*DD + d)*LL;
    for (int i = threadIdx.x; i < LL; i += blockDim.x)
        sm[(i/WW)*57 + (i%WW)] = src[i];
    __syncthreads();
    for (int i = threadIdx.x; i < LL; i += blockDim.x)
        dst[i] = sm[(i%WW)*57 + (i/WW)];
}

// ---------------- kernel 2: projections -------------------------------------
__device__ __forceinline__ float softplus_f(float x) {
    return (x > 20.f) ? x : log1pf(expf(x));
}

#define PROJ_THREADS 288

__global__ void __launch_bounds__(PROJ_THREADS, 1)
k_proj(const float* __restrict__ x1, const float* __restrict__ x2,
       const float* __restrict__ pw1, const float* __restrict__ pw2,
       const float* __restrict__ dtw1, const float* __restrict__ dtw2,
       const float* __restrict__ bias1, const float* __restrict__ bias2) {
    __shared__ __align__(16) float Xs[DD*XPITCH];
    __shared__ __align__(16) float dbl[CDIM*XPITCH];

    int bi = blockIdx.x;
    int tile = bi % NTILE;
    int k = (bi / NTILE) % KK;
    int b = (bi / (NTILE*KK)) % BB;
    int s = bi / (NTILE*KK*BB);
    int l0 = tile * TL;
    bool rev = (k >= 2);

    const float* xsrc = (s == 0) ? x1 : x2;
    const float* src = (k & 1) ? (g_xT + (size_t)(s*BB + b)*DD*LL)
                               : (xsrc + (size_t)b*DD*LL);
    const float* pw   = ((s == 0) ? pw1  : pw2)  + (size_t)k*CDIM*DD;
    const float* dtw  = ((s == 0) ? dtw1 : dtw2) + (size_t)k*DD*RR;
    const float* bias = ((s == 0) ? bias1: bias2) + (size_t)k*DD;

    // load X tile [D][XPITCH], zero-padding j>=TL
    for (int i = threadIdx.x; i < DD*XPITCH; i += blockDim.x) {
        int d = i / XPITCH, j = i % XPITCH;
        float v = 0.f;
        if (j < TL) {
            int l = rev ? (LL - 1 - (l0 + j)) : (l0 + j);
            v = src[(size_t)d*LL + l];
        }
        Xs[i] = v;
    }
    __syncthreads();

    // P1: 4c x 2j register tile over d (float4 weights, float2 X)
    {
        const int NCT = CDIM/4;    // 11
        const int NJT = XPITCH/2;  // 26
        for (int item = threadIdx.x; item < NCT*NJT; item += blockDim.x) {
            int ct = item / NJT, jt = item % NJT;
            int c0 = ct*4, j0 = jt*2;
            const float* w0 = pw + (c0+0)*DD;
            const float* w1 = pw + (c0+1)*DD;
            const float* w2 = pw + (c0+2)*DD;
            const float* w3 = pw + (c0+3)*DD;
            float a00=0.f,a01=0.f,a10=0.f,a11=0.f,a20=0.f,a21=0.f,a30=0.f,a31=0.f;
            #pragma unroll 2
            for (int d = 0; d < DD; d += 4) {
                float4 p0 = *reinterpret_cast<const float4*>(w0 + d);
                float4 p1 = *reinterpret_cast<const float4*>(w1 + d);
                float4 p2 = *reinterpret_cast<const float4*>(w2 + d);
                float4 p3 = *reinterpret_cast<const float4*>(w3 + d);
                float2 x0 = *reinterpret_cast<const float2*>(&Xs[(d+0)*XPITCH + j0]);
                float2 x1v = *reinterpret_cast<const float2*>(&Xs[(d+1)*XPITCH + j0]);
                float2 x2v = *reinterpret_cast<const float2*>(&Xs[(d+2)*XPITCH + j0]);
                float2 x3v = *reinterpret_cast<const float2*>(&Xs[(d+3)*XPITCH + j0]);
                a00 += p0.x*x0.x + p0.y*x1v.x + p0.z*x2v.x + p0.w*x3v.x;
                a01 += p0.x*x0.y + p0.y*x1v.y + p0.z*x2v.y + p0.w*x3v.y;
                a10 += p1.x*x0.x + p1.y*x1v.x + p1.z*x2v.x + p1.w*x3v.x;
                a11 += p1.x*x0.y + p1.y*x1v.y + p1.z*x2v.y + p1.w*x3v.y;
                a20 += p2.x*x0.x + p2.y*x1v.x + p2.z*x2v.x + p2.w*x3v.x;
                a21 += p2.x*x0.y + p2.y*x1v.y + p2.z*x2v.y + p2.w*x3v.y;
                a30 += p3.x*x0.x + p3.y*x1v.x + p3.z*x2v.x + p3.w*x3v.x;
                a31 += p3.x*x0.y + p3.y*x1v.y + p3.z*x2v.y + p3.w*x3v.y;
            }
            dbl[(c0+0)*XPITCH + j0]   = a00; dbl[(c0+0)*XPITCH + j0+1] = a01;
            dbl[(c0+1)*XPITCH + j0]   = a10; dbl[(c0+1)*XPITCH + j0+1] = a11;
            dbl[(c0+2)*XPITCH + j0]   = a20; dbl[(c0+2)*XPITCH + j0+1] = a21;
            dbl[(c0+3)*XPITCH + j0]   = a30; dbl[(c0+3)*XPITCH + j0+1] = a31;
        }
    }
    __syncthreads();

    size_t base = (size_t)((s*BB + b)*KK + k)*LL + l0;

    // P2: delta + u emit
    if (threadIdx.x < DD) {
        int d = threadIdx.x;
        float wr[RR];
        #pragma unroll
        for (int r = 0; r < RR; r++) wr[r] = dtw[d*RR + r];
        float bs = bias[d];
        for (int j = 0; j < TL; j++) {
            float acc = bs;
            #pragma unroll
            for (int r = 0; r < RR; r++) acc += wr[r] * dbl[r*XPITCH + j];
            g_delta[(base + j)*DD + d] = softplus_f(acc);
            g_u[(base + j)*DD + d]     = Xs[d*XPITCH + j];
        }
    } else if (threadIdx.x < DD + 32) {
        int t = threadIdx.x - DD;
        int n = t % NN;
        int which = t / NN;
        float* dst = which ? g_Cm : g_Bm;
        int row = RR + which*NN + n;
        for (int j = 0; j < TL; j++)
            dst[(base + j)*NN + n] = dbl[row*XPITCH + j];
    }
}

// ---------------- kernel 3: scan pass 1 -------------------------------------
__global__ void __launch_bounds__(DD, 6)
k_scan1() {
    __shared__ __align__(16) float Bt[TC*NN];
    int bi = blockIdx.x;
    int c = bi % NCH;
    int k = (bi / NCH) % KK;
    int b = (bi / (NCH*KK)) % BB;
    int s = bi / (NCH*KK*BB);
    int d = threadIdx.x;
    int sbk = (s*BB + b)*KK + k;

    const float* gB = g_Bm + ((size_t)sbk*LL + (size_t)c*TC)*NN;
    for (int i = threadIdx.x; i < TC*NN; i += blockDim.x) Bt[i] = gB[i];

    const float4* A4 = reinterpret_cast<const float4*>(g_A + (size_t)((s*KK + k)*DD + d)*NN);
    float4 a0 = A4[0], a1 = A4[1], a2 = A4[2], a3 = A4[3];
    float A[NN] = {a0.x,a0.y,a0.z,a0.w, a1.x,a1.y,a1.z,a1.w,
                   a2.x,a2.y,a2.z,a2.w, a3.x,a3.y,a3.z,a3.w};
    float h[NN];
    #pragma unroll
    for (int n = 0; n < NN; n++) h[n] = 0.f;
    float sd = 0.f;
    __syncthreads();

    const float* gd = g_delta + ((size_t)sbk*LL + (size_t)c*TC)*DD + d;
    const float* gu = g_u     + ((size_t)sbk*LL + (size_t)c*TC)*DD + d;

    for (int g = 0; g < TC/TG; g++) {
        float dl[TG], ul[TG];
        #pragma unroll
        for (int q = 0; q < TG; q++) { dl[q] = gd[q*DD]; ul[q] = gu[q*DD]; }
        gd += TG*DD; gu += TG*DD;
        #pragma unroll
        for (int q = 0; q < TG; q++) {
            float delta = dl[q];
            float du = delta * ul[q];
            sd += delta;
            const float4* B4 = reinterpret_cast<const float4*>(&Bt[(g*TG+q)*NN]);
            float4 b0 = B4[0], b1 = B4[1], b2 = B4[2], b3 = B4[3];
            float bt[NN] = {b0.x,b0.y,b0.z,b0.w, b1.x,b1.y,b1.z,b1.w,
                            b2.x,b2.y,b2.z,b2.w, b3.x,b3.y,b3.z,b3.w};
            #pragma unroll
            for (int n = 0; n < NN; n++)
                h[n] = exp2f(delta * A[n]) * h[n] + du * bt[n];
        }
    }

    size_t seq = (size_t)sbk*DD + d;
    float* cr = g_carry + (seq*NCH + c)*2*NN;
    float4* cr4 = reinterpret_cast<float4*>(cr);
    #pragma unroll
    for (int q = 0; q < 4; q++)
        cr4[q] = make_float4(h[4*q], h[4*q+1], h[4*q+2], h[4*q+3]);
    #pragma unroll
    for (int q = 0; q < 4; q++)
        cr4[4+q] = make_float4(exp2f(A[4*q]*sd), exp2f(A[4*q+1]*sd),
                               exp2f(A[4*q+2]*sd), exp2f(A[4*q+3]*sd));
}

// ---------------- kernel 4: fold chunk carries ------------------------------
__global__ void k_scan2() {
    int g = blockIdx.x*blockDim.x + threadIdx.x;
    if (g >= 2*BB*KK*DD*NN) return;
    int seq = g / NN, n = g % NN;
    float h = 0.f;
    for (int c = 0; c < NCH; c++) {
        g_hin[((size_t)seq*NCH + c)*NN + n] = h;
        const float* cr = g_carry + ((size_t)seq*NCH + c)*2*NN;
        h = cr[n] + cr[NN + n] * h;
    }
}

// ---------------- kernel 5: scan pass 3 (emit y) ----------------------------
__global__ void __launch_bounds__(DD, 6)
k_scan3(const float* __restrict__ D1s, const float* __restrict__ D2s) {
    __shared__ __align__(16) float Bt[TC*NN];
    __shared__ __align__(16) float Ct[TC*NN];
    int bi = blockIdx.x;
    int c = bi % NCH;
    int k = (bi / NCH) % KK;
    int b = (bi / (NCH*KK)) % BB;
    int s = bi / (NCH*KK*BB);
    int d = threadIdx.x;
    int sbk  = (s*BB + b)*KK + k;
    int sbkC = ((s^1)*BB + b)*KK + k;

    const float* gB = g_Bm + ((size_t)sbk*LL  + (size_t)c*TC)*NN;
    const float* gC = g_Cm + ((size_t)sbkC*LL + (size_t)c*TC)*NN;
    for (int i = threadIdx.x; i < TC*NN; i += blockDim.x) { Bt[i] = gB[i]; Ct[i] = gC[i]; }

    float Dp = ((s == 0) ? D1s : D2s)[k*DD + d];

    size_t seq = (size_t)sbk*DD + d;
    const float4* hi4 = reinterpret_cast<const float4*>(g_hin + (seq*NCH + c)*NN);
    float4 h0 = hi4[0], h1 = hi4[1], h2 = hi4[2], h3 = hi4[3];
    float h[NN] = {h0.x,h0.y,h0.z,h0.w, h1.x,h1.y,h1.z,h1.w,
                   h2.x,h2.y,h2.z,h2.w, h3.x,h3.y,h3.z,h3.w};
    const float4* A4 = reinterpret_cast<const float4*>(g_A + (size_t)((s*KK + k)*DD + d)*NN);
    float4 a0 = A4[0], a1 = A4[1], a2 = A4[2], a3 = A4[3];
    float A[NN] = {a0.x,a0.y,a0.z,a0.w, a1.x,a1.y,a1.z,a1.w,
                   a2.x,a2.y,a2.z,a2.w, a3.x,a3.y,a3.z,a3.w};
    __syncthreads();

    const float* gd = g_delta + ((size_t)sbk*LL + (size_t)c*TC)*DD + d;
    const float* gu = g_u     + ((size_t)sbk*LL + (size_t)c*TC)*DD + d;
    float* gy       = g_ys    + ((size_t)sbk*LL + (size_t)c*TC)*DD + d;

    for (int g = 0; g < TC/TG; g++) {
        float dl[TG], ul[TG];
        #pragma unroll
        for (int q = 0; q < TG; q++) { dl[q] = gd[q*DD]; ul[q] = gu[q*DD]; }
        gd += TG*DD; gu += TG*DD;
        #pragma unroll
        for (int q = 0; q < TG; q++) {
            float delta = dl[q];
            float u = ul[q];
            float du = delta * u;
            const float4* B4 = reinterpret_cast<const float4*>(&Bt[(g*TG+q)*NN]);
            const float4* C4 = reinterpret_cast<const float4*>(&Ct[(g*TG+q)*NN]);
            float4 b0 = B4[0], b1 = B4[1], b2 = B4[2], b3 = B4[3];
            float4 c0 = C4[0], c1 = C4[1], c2 = C4[2], c3 = C4[3];
            float bt[NN] = {b0.x,b0.y,b0.z,b0.w, b1.x,b1.y,b1.z,b1.w,
                            b2.x,b2.y,b2.z,b2.w, b3.x,b3.y,b3.z,b3.w};
            float ct[NN] = {c0.x,c0.y,c0.z,c0.w, c1.x,c1.y,c1.z,c1.w,
                            c2.x,c2.y,c2.z,c2.w, c3.x,c3.y,c3.z,c3.w};
            float y = Dp * u;
            #pragma unroll
            for (int n = 0; n < NN; n++) {
                h[n] = exp2f(delta * A[n]) * h[n] + du * bt[n];
                y += h[n] * ct[n];
            }
            gy[q*DD] = y;
        }
        gy += TG*DD;
    }
}

// ---------------- kernel 6: cross-merge + LayerNorm -------------------------
__global__ void k_merge(const float* __restrict__ lnw, const float* __restrict__ lnb,
                        float* __restrict__ out) {
    int wg = blockIdx.x*(blockDim.x/32) + (threadIdx.x >> 5);
    int lane = threadIdx.x & 31;
    int l = wg % LL;
    int b = (wg / LL) % BB;
    int s = wg / (LL*BB);
    int r = l / WW, cc = l % WW;
    int lt = cc*HH + r;
    size_t base = (size_t)(s*BB + b)*KK;

    float v[6];
    float sum = 0.f, sq = 0.f;
    #pragma unroll
    for (int j = 0; j < 6; j++) {
        int d = lane + j*32;
        float t = g_ys[((base + 0)*LL + l)*DD + d]
                + g_ys[((base + 2)*LL + (LL - 1 - l))*DD + d]
                + g_ys[((base + 1)*LL + lt)*DD + d]
                + g_ys[((base + 3)*LL + (LL - 1 - lt))*DD + d];
        v[j] = t; sum += t; sq += t*t;
    }
    #pragma unroll
    for (int o = 16; o; o >>= 1) {
        sum += __shfl_xor_sync(0xFFFFFFFFu, sum, o);
        sq  += __shfl_xor_sync(0xFFFFFFFFu, sq, o);
    }
    float mean = sum * (1.f/DD);
    float var  = sq * (1.f/DD) - mean*mean;
    float rstd = rsqrtf(var + 1e-5f);
    #pragma unroll
    for (int j = 0; j < 6; j++) {
        int d = lane + j*32;
        out[((size_t)(s*BB + b)*LL + l)*DD + d] = (v[j] - mean)*rstd*lnw[d] + lnb[d];
    }
}

// ---------------- launch ----------------------------------------------------
extern "C" void kernel_launch(void* const* d_in, const int* in_sizes, int n_in,
                              void* d_out, int out_size) {
    const float* x1   = (const float*)d_in[0];
    const float* x2   = (const float*)d_in[1];
    const float* pw1  = (const float*)d_in[2];
    const float* pw2  = (const float*)d_in[3];
    const float* dtw1 = (const float*)d_in[4];
    const float* dtw2 = (const float*)d_in[5];
    const float* b1   = (const float*)d_in[6];
    const float* b2   = (const float*)d_in[7];
    const float* A1   = (const float*)d_in[8];
    const float* A2   = (const float*)d_in[9];
    const float* D1   = (const float*)d_in[10];
    const float* D2   = (const float*)d_in[11];
    const float* lnw  = (const float*)d_in[12];
    const float* lnb  = (const float*)d_in[13];
    float* out = (float*)d_out;

    k_prepA<<<(2*KK*DD*NN + 255)/256, 256>>>(A1, A2);
    k_transpose<<<2*BB*DD, 256>>>(x1, x2);
    k_proj<<<2*BB*KK*NTILE, PROJ_THREADS>>>(x1, x2, pw1, pw2, dtw1, dtw2, b1, b2);
    k_scan1<<<2*BB*KK*NCH, DD>>>();
    k_scan2<<<(2*BB*KK*DD*NN + 255)/256, 256>>>();
    k_scan3<<<2*BB*KK*NCH, DD>>>(D1, D2);
    k_merge<<<(2*BB*LL)/8, 256>>>(lnw, lnb, out);
}

// round 12
// speedup vs baseline: 1.1084x; 1.1084x over previous
#include <cuda_runtime.h>

#define BB 2
#define DD 192
#define HH 56
#define WW 56
#define LL 3136
#define NN 16
#define RR 12
#define KK 4
#define CDIM 44   /* R + 2N */

#define TL 49     /* proj tile length; 64 tiles * 49 = 3136 */
#define NTILE 64
#define XPITCH 52 /* smem pitch (even, mult of 4) */

#define TC 28     /* scan chunk length */
#define NCH 112   /* 112 * 28 = 3136 */
#define TG 4      /* load-pipeline group: 28 = 7*4 */

#define LOG2E 1.44269504088896341f

// ---------------- scratch (device globals; no runtime alloc) ----------------
__device__ float g_xT[2*BB*DD*LL];
__device__ float g_u[2*(size_t)BB*KK*LL*DD];
__device__ float g_delta[2*(size_t)BB*KK*LL*DD];
__device__ float g_Bm[2*BB*KK*LL*NN];
__device__ float g_Cm[2*BB*KK*LL*NN];
__device__ float g_ys[2*(size_t)BB*KK*LL*DD];
__device__ float g_carry[2*(size_t)BB*KK*DD*NCH*2*NN];
__device__ float g_hin[2*(size_t)BB*KK*DD*NCH*NN];
__device__ float g_A[2*KK*DD*NN];

// ---------------- kernel 0: precompute A ------------------------------------
__global__ void k_prepA(const float* __restrict__ A1logs, const float* __restrict__ A2logs) {
    int g = blockIdx.x*blockDim.x + threadIdx.x;
    if (g >= 2*KK*DD*NN) return;
    int s = g / (KK*DD*NN);
    int rem = g % (KK*DD*NN);
    const float* src = (s == 0) ? A1logs : A2logs;
    g_A[g] = -expf(src[rem]) * LOG2E;
}

// ---------------- kernel 1: spatial transpose -------------------------------
__global__ void k_transpose(const float* __restrict__ x1, const float* __restrict__ x2) {
    __shared__ float sm[HH*57];
    int bi = blockIdx.x;
    int d = bi % DD;
    int b = (bi / DD) % BB;
    int s = bi / (DD*BB);
    const float* src = ((s == 0) ? x1 : x2) + ((size_t)b*DD + d)*LL;
    float* dst = g_xT + ((size_t)(s*BB + b)*DD + d)*LL;
    for (int i = threadIdx.x; i < LL; i += blockDim.x)
        sm[(i/WW)*57 + (i%WW)] = src[i];
    __syncthreads();
    for (int i = threadIdx.x; i < LL; i += blockDim.x)
        dst[i] = sm[(i%WW)*57 + (i/WW)];
}

// ---------------- kernel 2: projections -------------------------------------
__device__ __forceinline__ float softplus_f(float x) {
    return (x > 20.f) ? x : log1pf(expf(x));
}

#define PROJ_THREADS 288

__global__ void __launch_bounds__(PROJ_THREADS, 1)
k_proj(const float* __restrict__ x1, const float* __restrict__ x2,
       const float* __restrict__ pw1, const float* __restrict__ pw2,
       const float* __restrict__ dtw1, const float* __restrict__ dtw2,
       const float* __restrict__ bias1, const float* __restrict__ bias2) {
    __shared__ __align__(16) float Xs[DD*XPITCH];
    __shared__ __align__(16) float dbl[CDIM*XPITCH];

    int bi = blockIdx.x;
    int tile = bi % NTILE;
    int k = (bi / NTILE) % KK;
    int b = (bi / (NTILE*KK)) % BB;
    int s = bi / (NTILE*KK*BB);
    int l0 = tile * TL;
    bool rev = (k >= 2);

    const float* xsrc = (s == 0) ? x1 : x2;
    const float* src = (k & 1) ? (g_xT + (size_t)(s*BB + b)*DD*LL)
                               : (xsrc + (size_t)b*DD*LL);
    const float* pw   = ((s == 0) ? pw1  : pw2)  + (size_t)k*CDIM*DD;
    const float* dtw  = ((s == 0) ? dtw1 : dtw2) + (size_t)k*DD*RR;
    const float* bias = ((s == 0) ? bias1: bias2) + (size_t)k*DD;

    // load X tile [D][XPITCH], zero-padding j>=TL
    for (int i = threadIdx.x; i < DD*XPITCH; i += blockDim.x) {
        int d = i / XPITCH, j = i % XPITCH;
        float v = 0.f;
        if (j < TL) {
            int l = rev ? (LL - 1 - (l0 + j)) : (l0 + j);
            v = src[(size_t)d*LL + l];
        }
        Xs[i] = v;
    }
    __syncthreads();

    // P1: 4c x 2j register tile over d (float4 weights, float2 X)
    {
        const int NCT = CDIM/4;    // 11
        const int NJT = XPITCH/2;  // 26
        for (int item = threadIdx.x; item < NCT*NJT; item += blockDim.x) {
            int ct = item / NJT, jt = item % NJT;
            int c0 = ct*4, j0 = jt*2;
            const float* w0 = pw + (c0+0)*DD;
            const float* w1 = pw + (c0+1)*DD;
            const float* w2 = pw + (c0+2)*DD;
            const float* w3 = pw + (c0+3)*DD;
            float a00=0.f,a01=0.f,a10=0.f,a11=0.f,a20=0.f,a21=0.f,a30=0.f,a31=0.f;
            #pragma unroll 2
            for (int d = 0; d < DD; d += 4) {
                float4 p0 = *reinterpret_cast<const float4*>(w0 + d);
                float4 p1 = *reinterpret_cast<const float4*>(w1 + d);
                float4 p2 = *reinterpret_cast<const float4*>(w2 + d);
                float4 p3 = *reinterpret_cast<const float4*>(w3 + d);
                float2 x0 = *reinterpret_cast<const float2*>(&Xs[(d+0)*XPITCH + j0]);
                float2 x1v = *reinterpret_cast<const float2*>(&Xs[(d+1)*XPITCH + j0]);
                float2 x2v = *reinterpret_cast<const float2*>(&Xs[(d+2)*XPITCH + j0]);
                float2 x3v = *reinterpret_cast<const float2*>(&Xs[(d+3)*XPITCH + j0]);
                a00 += p0.x*x0.x + p0.y*x1v.x + p0.z*x2v.x + p0.w*x3v.x;
                a01 += p0.x*x0.y + p0.y*x1v.y + p0.z*x2v.y + p0.w*x3v.y;
                a10 += p1.x*x0.x + p1.y*x1v.x + p1.z*x2v.x + p1.w*x3v.x;
                a11 += p1.x*x0.y + p1.y*x1v.y + p1.z*x2v.y + p1.w*x3v.y;
                a20 += p2.x*x0.x + p2.y*x1v.x + p2.z*x2v.x + p2.w*x3v.x;
                a21 += p2.x*x0.y + p2.y*x1v.y + p2.z*x2v.y + p2.w*x3v.y;
                a30 += p3.x*x0.x + p3.y*x1v.x + p3.z*x2v.x + p3.w*x3v.x;
                a31 += p3.x*x0.y + p3.y*x1v.y + p3.z*x2v.y + p3.w*x3v.y;
            }
            dbl[(c0+0)*XPITCH + j0]   = a00; dbl[(c0+0)*XPITCH + j0+1] = a01;
            dbl[(c0+1)*XPITCH + j0]   = a10; dbl[(c0+1)*XPITCH + j0+1] = a11;
            dbl[(c0+2)*XPITCH + j0]   = a20; dbl[(c0+2)*XPITCH + j0+1] = a21;
            dbl[(c0+3)*XPITCH + j0]   = a30; dbl[(c0+3)*XPITCH + j0+1] = a31;
        }
    }
    __syncthreads();

    size_t base = (size_t)((s*BB + b)*KK + k)*LL + l0;

    // P2: delta + u emit
    if (threadIdx.x < DD) {
        int d = threadIdx.x;
        float wr[RR];
        #pragma unroll
        for (int r = 0; r < RR; r++) wr[r] = dtw[d*RR + r];
        float bs = bias[d];
        for (int j = 0; j < TL; j++) {
            float acc = bs;
            #pragma unroll
            for (int r = 0; r < RR; r++) acc += wr[r] * dbl[r*XPITCH + j];
            g_delta[(base + j)*DD + d] = softplus_f(acc);
            g_u[(base + j)*DD + d]     = Xs[d*XPITCH + j];
        }
    } else if (threadIdx.x < DD + 32) {
        int t = threadIdx.x - DD;
        int n = t % NN;
        int which = t / NN;
        float* dst = which ? g_Cm : g_Bm;
        int row = RR + which*NN + n;
        for (int j = 0; j < TL; j++)
            dst[(base + j)*NN + n] = dbl[row*XPITCH + j];
    }
}

// ---------------- kernel 3: scan pass 1 -------------------------------------
__global__ void __launch_bounds__(DD, 6)
k_scan1() {
    __shared__ __align__(16) float Bt[TC*NN];
    int bi = blockIdx.x;
    int c = bi % NCH;
    int k = (bi / NCH) % KK;
    int b = (bi / (NCH*KK)) % BB;
    int s = bi / (NCH*KK*BB);
    int d = threadIdx.x;
    int sbk = (s*BB + b)*KK + k;

    const float* gB = g_Bm + ((size_t)sbk*LL + (size_t)c*TC)*NN;
    for (int i = threadIdx.x; i < TC*NN; i += blockDim.x) Bt[i] = gB[i];

    const float4* A4 = reinterpret_cast<const float4*>(g_A + (size_t)((s*KK + k)*DD + d)*NN);
    float4 a0 = A4[0], a1 = A4[1], a2 = A4[2], a3 = A4[3];
    float A[NN] = {a0.x,a0.y,a0.z,a0.w, a1.x,a1.y,a1.z,a1.w,
                   a2.x,a2.y,a2.z,a2.w, a3.x,a3.y,a3.z,a3.w};
    float h[NN];
    #pragma unroll
    for (int n = 0; n < NN; n++) h[n] = 0.f;
    float sd = 0.f;
    __syncthreads();

    const float* gd = g_delta + ((size_t)sbk*LL + (size_t)c*TC)*DD + d;
    const float* gu = g_u     + ((size_t)sbk*LL + (size_t)c*TC)*DD + d;

    for (int g = 0; g < TC/TG; g++) {
        float dl[TG], ul[TG];
        #pragma unroll
        for (int q = 0; q < TG; q++) { dl[q] = gd[q*DD]; ul[q] = gu[q*DD]; }
        gd += TG*DD; gu += TG*DD;
        #pragma unroll
        for (int q = 0; q < TG; q++) {
            float delta = dl[q];
            float du = delta * ul[q];
            sd += delta;
            const float4* B4 = reinterpret_cast<const float4*>(&Bt[(g*TG+q)*NN]);
            float4 b0 = B4[0], b1 = B4[1], b2 = B4[2], b3 = B4[3];
            float bt[NN] = {b0.x,b0.y,b0.z,b0.w, b1.x,b1.y,b1.z,b1.w,
                            b2.x,b2.y,b2.z,b2.w, b3.x,b3.y,b3.z,b3.w};
            #pragma unroll
            for (int n = 0; n < NN; n++)
                h[n] = exp2f(delta * A[n]) * h[n] + du * bt[n];
        }
    }

    size_t seq = (size_t)sbk*DD + d;
    float* cr = g_carry + (seq*NCH + c)*2*NN;
    float4* cr4 = reinterpret_cast<float4*>(cr);
    #pragma unroll
    for (int q = 0; q < 4; q++)
        cr4[q] = make_float4(h[4*q], h[4*q+1], h[4*q+2], h[4*q+3]);
    #pragma unroll
    for (int q = 0; q < 4; q++)
        cr4[4+q] = make_float4(exp2f(A[4*q]*sd), exp2f(A[4*q+1]*sd),
                               exp2f(A[4*q+2]*sd), exp2f(A[4*q+3]*sd));
}

// ---------------- kernel 4: fold chunk carries (unrolled, MLP) ---------------
__global__ void k_scan2() {
    int g = blockIdx.x*blockDim.x + threadIdx.x;
    if (g >= 2*BB*KK*DD*NN) return;
    int seq = g / NN, n = g % NN;
    const float* crb = g_carry + (size_t)seq*NCH*2*NN;
    float* hob = g_hin + (size_t)seq*NCH*NN;
    float h = 0.f;
    for (int c0 = 0; c0 < NCH; c0 += 4) {
        float hv[4], pv[4];
        #pragma unroll
        for (int q = 0; q < 4; q++) {
            hv[q] = crb[(c0+q)*2*NN + n];
            pv[q] = crb[(c0+q)*2*NN + NN + n];
        }
        #pragma unroll
        for (int q = 0; q < 4; q++) {
            hob[(c0+q)*NN + n] = h;
            h = hv[q] + pv[q] * h;
        }
    }
}

// ---------------- kernel 5: scan pass 3 (emit y) ----------------------------
__global__ void __launch_bounds__(DD, 5)
k_scan3(const float* __restrict__ D1s, const float* __restrict__ D2s) {
    __shared__ __align__(16) float Bt[TC*NN];
    __shared__ __align__(16) float Ct[TC*NN];
    int bi = blockIdx.x;
    int c = bi % NCH;
    int k = (bi / NCH) % KK;
    int b = (bi / (NCH*KK)) % BB;
    int s = bi / (NCH*KK*BB);
    int d = threadIdx.x;
    int sbk  = (s*BB + b)*KK + k;
    int sbkC = ((s^1)*BB + b)*KK + k;

    const float* gB = g_Bm + ((size_t)sbk*LL  + (size_t)c*TC)*NN;
    const float* gC = g_Cm + ((size_t)sbkC*LL + (size_t)c*TC)*NN;
    for (int i = threadIdx.x; i < TC*NN; i += blockDim.x) { Bt[i] = gB[i]; Ct[i] = gC[i]; }

    float Dp = ((s == 0) ? D1s : D2s)[k*DD + d];

    size_t seq = (size_t)sbk*DD + d;
    const float4* hi4 = reinterpret_cast<const float4*>(g_hin + (seq*NCH + c)*NN);
    float4 h0 = hi4[0], h1 = hi4[1], h2 = hi4[2], h3 = hi4[3];
    float h[NN] = {h0.x,h0.y,h0.z,h0.w, h1.x,h1.y,h1.z,h1.w,
                   h2.x,h2.y,h2.z,h2.w, h3.x,h3.y,h3.z,h3.w};
    const float4* A4 = reinterpret_cast<const float4*>(g_A + (size_t)((s*KK + k)*DD + d)*NN);
    float4 a0 = A4[0], a1 = A4[1], a2 = A4[2], a3 = A4[3];
    float A[NN] = {a0.x,a0.y,a0.z,a0.w, a1.x,a1.y,a1.z,a1.w,
                   a2.x,a2.y,a2.z,a2.w, a3.x,a3.y,a3.z,a3.w};
    __syncthreads();

    const float* gd = g_delta + ((size_t)sbk*LL + (size_t)c*TC)*DD + d;
    const float* gu = g_u     + ((size_t)sbk*LL + (size_t)c*TC)*DD + d;
    float* gy       = g_ys    + ((size_t)sbk*LL + (size_t)c*TC)*DD + d;

    for (int g = 0; g < TC/TG; g++) {
        float dl[TG], ul[TG];
        #pragma unroll
        for (int q = 0; q < TG; q++) { dl[q] = gd[q*DD]; ul[q] = gu[q*DD]; }
        gd += TG*DD; gu += TG*DD;
        #pragma unroll
        for (int q = 0; q < TG; q++) {
            float delta = dl[q];
            float u = ul[q];
            float du = delta * u;
            const float4* B4 = reinterpret_cast<const float4*>(&Bt[(g*TG+q)*NN]);
            const float4* C4 = reinterpret_cast<const float4*>(&Ct[(g*TG+q)*NN]);
            float4 b0 = B4[0], b1 = B4[1], b2 = B4[2], b3 = B4[3];
            float4 c0 = C4[0], c1 = C4[1], c2 = C4[2], c3 = C4[3];
            float bt[NN] = {b0.x,b0.y,b0.z,b0.w, b1.x,b1.y,b1.z,b1.w,
                            b2.x,b2.y,b2.z,b2.w, b3.x,b3.y,b3.z,b3.w};
            float ct[NN] = {c0.x,c0.y,c0.z,c0.w, c1.x,c1.y,c1.z,c1.w,
                            c2.x,c2.y,c2.z,c2.w, c3.x,c3.y,c3.z,c3.w};
            float y = Dp * u;
            #pragma unroll
            for (int n = 0; n < NN; n++) {
                h[n] = exp2f(delta * A[n]) * h[n] + du * bt[n];
                y += h[n] * ct[n];
            }
            gy[q*DD] = y;
        }
        gy += TG*DD;
    }
}

// ---------------- kernel 6: cross-merge + LayerNorm -------------------------
__global__ void k_merge(const float* __restrict__ lnw, const float* __restrict__ lnb,
                        float* __restrict__ out) {
    int wg = blockIdx.x*(blockDim.x/32) + (threadIdx.x >> 5);
    int lane = threadIdx.x & 31;
    int l = wg % LL;
    int b = (wg / LL) % BB;
    int s = wg / (LL*BB);
    int r = l / WW, cc = l % WW;
    int lt = cc*HH + r;
    size_t base = (size_t)(s*BB + b)*KK;

    float v[6];
    float sum = 0.f, sq = 0.f;
    #pragma unroll
    for (int j = 0; j < 6; j++) {
        int d = lane + j*32;
        float t = g_ys[((base + 0)*LL + l)*DD + d]
                + g_ys[((base + 2)*LL + (LL - 1 - l))*DD + d]
                + g_ys[((base + 1)*LL + lt)*DD + d]
                + g_ys[((base + 3)*LL + (LL - 1 - lt))*DD + d];
        v[j] = t; sum += t; sq += t*t;
    }
    #pragma unroll
    for (int o = 16; o; o >>= 1) {
        sum += __shfl_xor_sync(0xFFFFFFFFu, sum, o);
        sq  += __shfl_xor_sync(0xFFFFFFFFu, sq, o);
    }
    float mean = sum * (1.f/DD);
    float var  = sq * (1.f/DD) - mean*mean;
    float rstd = rsqrtf(var + 1e-5f);
    #pragma unroll
    for (int j = 0; j < 6; j++) {
        int d = lane + j*32;
        out[((size_t)(s*BB + b)*LL + l)*DD + d] = (v[j] - mean)*rstd*lnw[d] + lnb[d];
    }
}

// ---------------- launch ----------------------------------------------------
extern "C" void kernel_launch(void* const* d_in, const int* in_sizes, int n_in,
                              void* d_out, int out_size) {
    const float* x1   = (const float*)d_in[0];
    const float* x2   = (const float*)d_in[1];
    const float* pw1  = (const float*)d_in[2];
    const float* pw2  = (const float*)d_in[3];
    const float* dtw1 = (const float*)d_in[4];
    const float* dtw2 = (const float*)d_in[5];
    const float* b1   = (const float*)d_in[6];
    const float* b2   = (const float*)d_in[7];
    const float* A1   = (const float*)d_in[8];
    const float* A2   = (const float*)d_in[9];
    const float* D1   = (const float*)d_in[10];
    const float* D2   = (const float*)d_in[11];
    const float* lnw  = (const float*)d_in[12];
    const float* lnb  = (const float*)d_in[13];
    float* out = (float*)d_out;

    k_prepA<<<(2*KK*DD*NN + 255)/256, 256>>>(A1, A2);
    k_transpose<<<2*BB*DD, 256>>>(x1, x2);
    k_proj<<<2*BB*KK*NTILE, PROJ_THREADS>>>(x1, x2, pw1, pw2, dtw1, dtw2, b1, b2);
    k_scan1<<<2*BB*KK*NCH, DD>>>();
    k_scan2<<<(2*BB*KK*DD*NN + 255)/256, 256>>>();
    k_scan3<<<2*BB*KK*NCH, DD>>>(D1, D2);
    k_merge<<<(2*BB*LL)/8, 256>>>(lnw, lnb, out);
}

// round 13
// speedup vs baseline: 1.1775x; 1.0624x over previous
#include <cuda_runtime.h>

#define BB 2
#define DD 192
#define HH 56
#define WW 56
#define LL 3136
#define NN 16
#define RR 12
#define KK 4
#define CDIM 44   /* R + 2N */

#define TL 49
#define NTILE 64
#define XPITCH 52

#define TC 28
#define NCH 112
#define TG 4

#define LOG2E 1.44269504088896341f

typedef unsigned long long ull;

// ---------------- packed f32x2 helpers (Blackwell) ---------------------------
__device__ __forceinline__ ull pk2(float a, float b) {
    ull r; asm("mov.b64 %0, {%1,%2};" : "=l"(r) : "f"(a), "f"(b)); return r;
}
__device__ __forceinline__ void upk2(ull v, float& a, float& b) {
    asm("mov.b64 {%0,%1}, %2;" : "=f"(a), "=f"(b) : "l"(v));
}
__device__ __forceinline__ ull mul2(ull a, ull b) {
    ull r; asm("mul.rn.f32x2 %0, %1, %2;" : "=l"(r) : "l"(a), "l"(b)); return r;
}
__device__ __forceinline__ ull fma2(ull a, ull b, ull c) {
    ull r; asm("fma.rn.f32x2 %0, %1, %2, %3;" : "=l"(r) : "l"(a), "l"(b), "l"(c)); return r;
}

// ---------------- scratch ----------------------------------------------------
__device__ float2 g_dta[2*(size_t)BB*KK*LL*DD];        // (delta, u) interleaved
__device__ float g_xT[2*BB*DD*LL];
__device__ float g_Bm[2*BB*KK*LL*NN];
__device__ float g_Cm[2*BB*KK*LL*NN];
__device__ float g_ys[2*(size_t)BB*KK*LL*DD];
__device__ float g_carry[2*(size_t)BB*KK*DD*NCH*2*NN];
__device__ float g_hin[2*(size_t)BB*KK*DD*NCH*NN];
__device__ float g_A[2*KK*DD*NN];

// ---------------- kernel 0: precompute A ------------------------------------
__global__ void k_prepA(const float* __restrict__ A1logs, const float* __restrict__ A2logs) {
    int g = blockIdx.x*blockDim.x + threadIdx.x;
    if (g >= 2*KK*DD*NN) return;
    int s = g / (KK*DD*NN);
    int rem = g % (KK*DD*NN);
    const float* src = (s == 0) ? A1logs : A2logs;
    g_A[g] = -expf(src[rem]) * LOG2E;
}

// ---------------- kernel 1: spatial transpose -------------------------------
__global__ void k_transpose(const float* __restrict__ x1, const float* __restrict__ x2) {
    __shared__ float sm[HH*57];
    int bi = blockIdx.x;
    int d = bi % DD;
    int b = (bi / DD) % BB;
    int s = bi / (DD*BB);
    const float* src = ((s == 0) ? x1 : x2) + ((size_t)b*DD + d)*LL;
    float* dst = g_xT + ((size_t)(s*BB + b)*DD + d)*LL;
    for (int i = threadIdx.x; i < LL; i += blockDim.x)
        sm[(i/WW)*57 + (i%WW)] = src[i];
    __syncthreads();
    for (int i = threadIdx.x; i < LL; i += blockDim.x)
        dst[i] = sm[(i%WW)*57 + (i/WW)];
}

// ---------------- kernel 2: projections -------------------------------------
__device__ __forceinline__ float softplus_f(float x) {
    return (x > 20.f) ? x : log1pf(expf(x));
}

#define PROJ_THREADS 288

__global__ void __launch_bounds__(PROJ_THREADS, 1)
k_proj(const float* __restrict__ x1, const float* __restrict__ x2,
       const float* __restrict__ pw1, const float* __restrict__ pw2,
       const float* __restrict__ dtw1, const float* __restrict__ dtw2,
       const float* __restrict__ bias1, const float* __restrict__ bias2) {
    __shared__ __align__(16) float Xs[DD*XPITCH];
    __shared__ __align__(16) float dbl[CDIM*XPITCH];

    int bi = blockIdx.x;
    int tile = bi % NTILE;
    int k = (bi / NTILE) % KK;
    int b = (bi / (NTILE*KK)) % BB;
    int s = bi / (NTILE*KK*BB);
    int l0 = tile * TL;
    bool rev = (k >= 2);

    const float* xsrc = (s == 0) ? x1 : x2;
    const float* src = (k & 1) ? (g_xT + (size_t)(s*BB + b)*DD*LL)
                               : (xsrc + (size_t)b*DD*LL);
    const float* pw   = ((s == 0) ? pw1  : pw2)  + (size_t)k*CDIM*DD;
    const float* dtw  = ((s == 0) ? dtw1 : dtw2) + (size_t)k*DD*RR;
    const float* bias = ((s == 0) ? bias1: bias2) + (size_t)k*DD;

    for (int i = threadIdx.x; i < DD*XPITCH; i += blockDim.x) {
        int d = i / XPITCH, j = i % XPITCH;
        float v = 0.f;
        if (j < TL) {
            int l = rev ? (LL - 1 - (l0 + j)) : (l0 + j);
            v = src[(size_t)d*LL + l];
        }
        Xs[i] = v;
    }
    __syncthreads();

    {
        const int NCT = CDIM/4;
        const int NJT = XPITCH/2;
        for (int item = threadIdx.x; item < NCT*NJT; item += blockDim.x) {
            int ct = item / NJT, jt = item % NJT;
            int c0 = ct*4, j0 = jt*2;
            const float* w0 = pw + (c0+0)*DD;
            const float* w1 = pw + (c0+1)*DD;
            const float* w2 = pw + (c0+2)*DD;
            const float* w3 = pw + (c0+3)*DD;
            float a00=0.f,a01=0.f,a10=0.f,a11=0.f,a20=0.f,a21=0.f,a30=0.f,a31=0.f;
            #pragma unroll 2
            for (int d = 0; d < DD; d += 4) {
                float4 p0 = *reinterpret_cast<const float4*>(w0 + d);
                float4 p1 = *reinterpret_cast<const float4*>(w1 + d);
                float4 p2 = *reinterpret_cast<const float4*>(w2 + d);
                float4 p3 = *reinterpret_cast<const float4*>(w3 + d);
                float2 x0 = *reinterpret_cast<const float2*>(&Xs[(d+0)*XPITCH + j0]);
                float2 x1v = *reinterpret_cast<const float2*>(&Xs[(d+1)*XPITCH + j0]);
                float2 x2v = *reinterpret_cast<const float2*>(&Xs[(d+2)*XPITCH + j0]);
                float2 x3v = *reinterpret_cast<const float2*>(&Xs[(d+3)*XPITCH + j0]);
                a00 += p0.x*x0.x + p0.y*x1v.x + p0.z*x2v.x + p0.w*x3v.x;
                a01 += p0.x*x0.y + p0.y*x1v.y + p0.z*x2v.y + p0.w*x3v.y;
                a10 += p1.x*x0.x + p1.y*x1v.x + p1.z*x2v.x + p1.w*x3v.x;
                a11 += p1.x*x0.y + p1.y*x1v.y + p1.z*x2v.y + p1.w*x3v.y;
                a20 += p2.x*x0.x + p2.y*x1v.x + p2.z*x2v.x + p2.w*x3v.x;
                a21 += p2.x*x0.y + p2.y*x1v.y + p2.z*x2v.y + p2.w*x3v.y;
                a30 += p3.x*x0.x + p3.y*x1v.x + p3.z*x2v.x + p3.w*x3v.x;
                a31 += p3.x*x0.y + p3.y*x1v.y + p3.z*x2v.y + p3.w*x3v.y;
            }
            dbl[(c0+0)*XPITCH + j0]   = a00; dbl[(c0+0)*XPITCH + j0+1] = a01;
            dbl[(c0+1)*XPITCH + j0]   = a10; dbl[(c0+1)*XPITCH + j0+1] = a11;
            dbl[(c0+2)*XPITCH + j0]   = a20; dbl[(c0+2)*XPITCH + j0+1] = a21;
            dbl[(c0+3)*XPITCH + j0]   = a30; dbl[(c0+3)*XPITCH + j0+1] = a31;
        }
    }
    __syncthreads();

    size_t base = (size_t)((s*BB + b)*KK + k)*LL + l0;

    if (threadIdx.x < DD) {
        int d = threadIdx.x;
        float wr[RR];
        #pragma unroll
        for (int r = 0; r < RR; r++) wr[r] = dtw[d*RR + r];
        float bs = bias[d];
        for (int j = 0; j < TL; j++) {
            float acc = bs;
            #pragma unroll
            for (int r = 0; r < RR; r++) acc += wr[r] * dbl[r*XPITCH + j];
            g_dta[(base + j)*DD + d] = make_float2(softplus_f(acc), Xs[d*XPITCH + j]);
        }
    } else if (threadIdx.x < DD + 32) {
        int t = threadIdx.x - DD;
        int n = t % NN;
        int which = t / NN;
        float* dst = which ? g_Cm : g_Bm;
        int row = RR + which*NN + n;
        for (int j = 0; j < TL; j++)
            dst[(base + j)*NN + n] = dbl[row*XPITCH + j];
    }
}

// ---------------- kernel 3: scan pass 1 (packed f32x2) -----------------------
__global__ void __launch_bounds__(DD, 6)
k_scan1() {
    __shared__ __align__(16) float Bt[TC*NN];
    int bi = blockIdx.x;
    int c = bi % NCH;
    int k = (bi / NCH) % KK;
    int b = (bi / (NCH*KK)) % BB;
    int s = bi / (NCH*KK*BB);
    int d = threadIdx.x;
    int sbk = (s*BB + b)*KK + k;

    const float* gB = g_Bm + ((size_t)sbk*LL + (size_t)c*TC)*NN;
    for (int i = threadIdx.x; i < TC*NN; i += blockDim.x) Bt[i] = gB[i];

    const float4* A4 = reinterpret_cast<const float4*>(g_A + (size_t)((s*KK + k)*DD + d)*NN);
    float4 a0 = A4[0], a1 = A4[1], a2 = A4[2], a3 = A4[3];
    ull A2[8] = { pk2(a0.x,a0.y), pk2(a0.z,a0.w), pk2(a1.x,a1.y), pk2(a1.z,a1.w),
                  pk2(a2.x,a2.y), pk2(a2.z,a2.w), pk2(a3.x,a3.y), pk2(a3.z,a3.w) };
    ull h2[8];
    #pragma unroll
    for (int j = 0; j < 8; j++) h2[j] = 0ull;
    float sd = 0.f;
    __syncthreads();

    const float2* gdta = g_dta + ((size_t)sbk*LL + (size_t)c*TC)*DD + d;

    for (int g = 0; g < TC/TG; g++) {
        float2 dv[TG];
        #pragma unroll
        for (int q = 0; q < TG; q++) dv[q] = gdta[q*DD];
        gdta += TG*DD;
        #pragma unroll
        for (int q = 0; q < TG; q++) {
            float delta = dv[q].x;
            float du = delta * dv[q].y;
            sd += delta;
            ull delta2 = pk2(delta, delta);
            ull du2 = pk2(du, du);
            const ulonglong2* B2 = reinterpret_cast<const ulonglong2*>(&Bt[(g*TG+q)*NN]);
            ulonglong2 bq0 = B2[0], bq1 = B2[1], bq2 = B2[2], bq3 = B2[3];
            ull bt2[8] = { bq0.x, bq0.y, bq1.x, bq1.y, bq2.x, bq2.y, bq3.x, bq3.y };
            #pragma unroll
            for (int j = 0; j < 8; j++) {
                float e0, e1;
                upk2(mul2(delta2, A2[j]), e0, e1);
                ull dA2 = pk2(exp2f(e0), exp2f(e1));
                h2[j] = fma2(dA2, h2[j], mul2(du2, bt2[j]));
            }
        }
    }

    size_t seq = (size_t)sbk*DD + d;
    float* cr = g_carry + (seq*NCH + c)*2*NN;
    float4* cr4 = reinterpret_cast<float4*>(cr);
    #pragma unroll
    for (int q = 0; q < 4; q++) {
        float h0, h1, h2v, h3;
        upk2(h2[2*q], h0, h1);
        upk2(h2[2*q+1], h2v, h3);
        cr4[q] = make_float4(h0, h1, h2v, h3);
    }
    #pragma unroll
    for (int q = 0; q < 4; q++) {
        float p0, p1, p2, p3;
        upk2(A2[2*q], p0, p1);
        upk2(A2[2*q+1], p2, p3);
        cr4[4+q] = make_float4(exp2f(p0*sd), exp2f(p1*sd), exp2f(p2*sd), exp2f(p3*sd));
    }
}

// ---------------- kernel 4: fold chunk carries -------------------------------
__global__ void k_scan2() {
    int g = blockIdx.x*blockDim.x + threadIdx.x;
    if (g >= 2*BB*KK*DD*NN) return;
    int seq = g / NN, n = g % NN;
    const float* crb = g_carry + (size_t)seq*NCH*2*NN;
    float* hob = g_hin + (size_t)seq*NCH*NN;
    float h = 0.f;
    for (int c0 = 0; c0 < NCH; c0 += 4) {
        float hv[4], pv[4];
        #pragma unroll
        for (int q = 0; q < 4; q++) {
            hv[q] = crb[(c0+q)*2*NN + n];
            pv[q] = crb[(c0+q)*2*NN + NN + n];
        }
        #pragma unroll
        for (int q = 0; q < 4; q++) {
            hob[(c0+q)*NN + n] = h;
            h = hv[q] + pv[q] * h;
        }
    }
}

// ---------------- kernel 5: scan pass 3 (packed f32x2, emit y) ---------------
__global__ void __launch_bounds__(DD, 5)
k_scan3(const float* __restrict__ D1s, const float* __restrict__ D2s) {
    __shared__ __align__(16) float Bt[TC*NN];
    __shared__ __align__(16) float Ct[TC*NN];
    int bi = blockIdx.x;
    int c = bi % NCH;
    int k = (bi / NCH) % KK;
    int b = (bi / (NCH*KK)) % BB;
    int s = bi / (NCH*KK*BB);
    int d = threadIdx.x;
    int sbk  = (s*BB + b)*KK + k;
    int sbkC = ((s^1)*BB + b)*KK + k;

    const float* gB = g_Bm + ((size_t)sbk*LL  + (size_t)c*TC)*NN;
    const float* gC = g_Cm + ((size_t)sbkC*LL + (size_t)c*TC)*NN;
    for (int i = threadIdx.x; i < TC*NN; i += blockDim.x) { Bt[i] = gB[i]; Ct[i] = gC[i]; }

    float Dp = ((s == 0) ? D1s : D2s)[k*DD + d];

    size_t seq = (size_t)sbk*DD + d;
    const float4* hi4 = reinterpret_cast<const float4*>(g_hin + (seq*NCH + c)*NN);
    float4 h0v = hi4[0], h1v = hi4[1], h2v = hi4[2], h3v = hi4[3];
    ull h2[8] = { pk2(h0v.x,h0v.y), pk2(h0v.z,h0v.w), pk2(h1v.x,h1v.y), pk2(h1v.z,h1v.w),
                  pk2(h2v.x,h2v.y), pk2(h2v.z,h2v.w), pk2(h3v.x,h3v.y), pk2(h3v.z,h3v.w) };
    const float4* A4 = reinterpret_cast<const float4*>(g_A + (size_t)((s*KK + k)*DD + d)*NN);
    float4 a0 = A4[0], a1 = A4[1], a2 = A4[2], a3 = A4[3];
    ull A2[8] = { pk2(a0.x,a0.y), pk2(a0.z,a0.w), pk2(a1.x,a1.y), pk2(a1.z,a1.w),
                  pk2(a2.x,a2.y), pk2(a2.z,a2.w), pk2(a3.x,a3.y), pk2(a3.z,a3.w) };
    __syncthreads();

    const float2* gdta = g_dta + ((size_t)sbk*LL + (size_t)c*TC)*DD + d;
    float* gy = g_ys + ((size_t)sbk*LL + (size_t)c*TC)*DD + d;

    for (int g = 0; g < TC/TG; g++) {
        float2 dv[TG];
        #pragma unroll
        for (int q = 0; q < TG; q++) dv[q] = gdta[q*DD];
        gdta += TG*DD;
        #pragma unroll
        for (int q = 0; q < TG; q++) {
            float delta = dv[q].x;
            float u = dv[q].y;
            float du = delta * u;
            ull delta2 = pk2(delta, delta);
            ull du2 = pk2(du, du);
            const ulonglong2* B2 = reinterpret_cast<const ulonglong2*>(&Bt[(g*TG+q)*NN]);
            const ulonglong2* C2 = reinterpret_cast<const ulonglong2*>(&Ct[(g*TG+q)*NN]);
            ulonglong2 bq0 = B2[0], bq1 = B2[1], bq2 = B2[2], bq3 = B2[3];
            ulonglong2 cq0 = C2[0], cq1 = C2[1], cq2 = C2[2], cq3 = C2[3];
            ull bt2[8] = { bq0.x, bq0.y, bq1.x, bq1.y, bq2.x, bq2.y, bq3.x, bq3.y };
            ull ct2[8] = { cq0.x, cq0.y, cq1.x, cq1.y, cq2.x, cq2.y, cq3.x, cq3.y };
            ull y2 = 0ull;
            #pragma unroll
            for (int j = 0; j < 8; j++) {
                float e0, e1;
                upk2(mul2(delta2, A2[j]), e0, e1);
                ull dA2 = pk2(exp2f(e0), exp2f(e1));
                h2[j] = fma2(dA2, h2[j], mul2(du2, bt2[j]));
                y2 = fma2(h2[j], ct2[j], y2);
            }
            float ylo, yhi;
            upk2(y2, ylo, yhi);
            gy[q*DD] = ylo + yhi + Dp * u;
        }
        gy += TG*DD;
    }
}

// ---------------- kernel 6: cross-merge + LayerNorm -------------------------
__global__ void k_merge(const float* __restrict__ lnw, const float* __restrict__ lnb,
                        float* __restrict__ out) {
    int wg = blockIdx.x*(blockDim.x/32) + (threadIdx.x >> 5);
    int lane = threadIdx.x & 31;
    int l = wg % LL;
    int b = (wg / LL) % BB;
    int s = wg / (LL*BB);
    int r = l / WW, cc = l % WW;
    int lt = cc*HH + r;
    size_t base = (size_t)(s*BB + b)*KK;

    float v[6];
    float sum = 0.f, sq = 0.f;
    #pragma unroll
    for (int j = 0; j < 6; j++) {
        int d = lane + j*32;
        float t = g_ys[((base + 0)*LL + l)*DD + d]
                + g_ys[((base + 2)*LL + (LL - 1 - l))*DD + d]
                + g_ys[((base + 1)*LL + lt)*DD + d]
                + g_ys[((base + 3)*LL + (LL - 1 - lt))*DD + d];
        v[j] = t; sum += t; sq += t*t;
    }
    #pragma unroll
    for (int o = 16; o; o >>= 1) {
        sum += __shfl_xor_sync(0xFFFFFFFFu, sum, o);
        sq  += __shfl_xor_sync(0xFFFFFFFFu, sq, o);
    }
    float mean = sum * (1.f/DD);
    float var  = sq * (1.f/DD) - mean*mean;
    float rstd = rsqrtf(var + 1e-5f);
    #pragma unroll
    for (int j = 0; j < 6; j++) {
        int d = lane + j*32;
        out[((size_t)(s*BB + b)*LL + l)*DD + d] = (v[j] - mean)*rstd*lnw[d] + lnb[d];
    }
}

// ---------------- launch ----------------------------------------------------
extern "C" void kernel_launch(void* const* d_in, const int* in_sizes, int n_in,
                              void* d_out, int out_size) {
    const float* x1   = (const float*)d_in[0];
    const float* x2   = (const float*)d_in[1];
    const float* pw1  = (const float*)d_in[2];
    const float* pw2  = (const float*)d_in[3];
    const float* dtw1 = (const float*)d_in[4];
    const float* dtw2 = (const float*)d_in[5];
    const float* b1   = (const float*)d_in[6];
    const float* b2   = (const float*)d_in[7];
    const float* A1   = (const float*)d_in[8];
    const float* A2in = (const float*)d_in[9];
    const float* D1   = (const float*)d_in[10];
    const float* D2   = (const float*)d_in[11];
    const float* lnw  = (const float*)d_in[12];
    const float* lnb  = (const float*)d_in[13];
    float* out = (float*)d_out;

    k_prepA<<<(2*KK*DD*NN + 255)/256, 256>>>(A1, A2in);
    k_transpose<<<2*BB*DD, 256>>>(x1, x2);
    k_proj<<<2*BB*KK*NTILE, PROJ_THREADS>>>(x1, x2, pw1, pw2, dtw1, dtw2, b1, b2);
    k_scan1<<<2*BB*KK*NCH, DD>>>();
    k_scan2<<<(2*BB*KK*DD*NN + 255)/256, 256>>>();
    k_scan3<<<2*BB*KK*NCH, DD>>>(D1, D2);
    k_merge<<<(2*BB*LL)/8, 256>>>(lnw, lnb, out);
}